// round 16
// baseline (speedup 1.0000x reference)
#include <cuda_runtime.h>
#include <cuda_fp16.h>
#include <math.h>

#define Wd 256
#define Hd 256
#define HW 65536
typedef unsigned int u32;

// ---------------- scratch (no allocation allowed) ----------------
__device__ float g_off [2 * 144 * HW];
__device__ float g_mask[2 * 72 * HW];
__device__ __align__(16) __half g_xt[2 * 64 * HW];           // NHWC feat per branch
__device__ __align__(16) __half g_ef_hi[2 * HW * 128];       // extra_feat hi/lo NHWC
__device__ __align__(16) __half g_ef_lo[2 * HW * 128];
__device__ __align__(16) __half g_cat_hi[HW * 128];          // mdcn out (both branches)
__device__ __align__(16) __half g_cat_lo[HW * 128];
__device__ __align__(16) __half g_act_hi[4 * HW * 64];       // [pp*2+branch]
__device__ __align__(16) __half g_act_lo[4 * HW * 64];
__device__ __align__(16) __half g_whi[663552];
__device__ __align__(16) __half g_wlo[663552];
__device__ __align__(16) __half g_dwhi[2 * 45056];
__device__ __align__(16) __half g_dwlo[2 * 45056];

// ---------------- merged conv-weight pre-convert ----------------
struct WSrc { const float* p[9]; };
__global__ void wprep_all(WSrc ws, __half* __restrict__ dhi, __half* __restrict__ dlo)
{
    const int off[9]  = {0,73728,110592,147456,294912,368640,405504,442368,589824};
    const int CINs[9] = {128,64,64,64,128,64,64,64,128};
    const int OCs[9]  = {64,64,64,216,64,64,64,216,64};
    const int OCp[9]  = {64,64,64,256,64,64,64,256,64};
    int idx = blockIdx.x * 256 + threadIdx.x;
    if (idx >= 663552) return;
    int seg = 0;
#pragma unroll
    for (int s = 1; s < 9; s++) if (idx >= off[s]) seg = s;
    int r = idx - off[seg];
    int per_t = OCp[seg] * CINs[seg];
    int t = r / per_t; r -= t * per_t;
    int o = r / CINs[seg], c = r - o * CINs[seg];
    float w = (o < OCs[seg]) ? ws.p[seg][(o * CINs[seg] + c) * 9 + t] : 0.f;
    __half h = __float2half_rn(w);
    dhi[idx] = h;
    dlo[idx] = __float2half_rn(w - __half2float(h));
}

// ---------------- dcn weight pre-convert ----------------
__global__ void dcnprep_all(const float* __restrict__ s1, const float* __restrict__ s2,
                            __half* __restrict__ dhi, __half* __restrict__ dlo)
{
    int idx = blockIdx.x * 256 + threadIdx.x;
    if (idx >= 45056) return;
    const float* src = blockIdx.y ? s2 : s1;
    int base = blockIdx.y * 45056;
    int g = idx / 5632, r = idx - g * 5632, o = r / 88, ck = r - o * 88;
    float w = 0.f;
    if (ck < 72) { int c = ck / 9, k = ck - c * 9; w = src[((size_t)o * 64 + g * 8 + c) * 9 + k]; }
    __half h = __float2half_rn(w);
    dhi[base + idx] = h;
    dlo[base + idx] = __float2half_rn(w - __half2float(h));
}

// ---------------- NCHW fp32 -> NHWC fp16 (feat for mdcn) ----------------
__global__ __launch_bounds__(128)
void tohwc_kernel(const float* __restrict__ s0, const float* __restrict__ s1,
                  __half* __restrict__ dst)
{
    __shared__ float s[64 * 130];
    const int t = threadIdx.x;
    const int pix0 = blockIdx.x * 128;
    const float* src = blockIdx.y ? s1 : s0;
    dst += (size_t)blockIdx.y * 64 * HW;
    for (int c = 0; c < 64; c++) s[c * 130 + t] = src[(size_t)c * HW + pix0 + t];
    __syncthreads();
    for (int i = 0; i < 64; i++) {
        int L = t + i * 128;
        dst[(size_t)pix0 * 64 + L] = __float2half_rn(s[(L & 63) * 130 + (L >> 6)]);
    }
}

// ---------------- extra_feat NCHW fp32 -> hi/lo NHWC (stride 128) ----------------
__global__ __launch_bounds__(128)
void efprep_kernel(const float* __restrict__ s0, const float* __restrict__ s1,
                   __half* __restrict__ dhi, __half* __restrict__ dlo)
{
    __shared__ float s[64 * 130];
    const int t = threadIdx.x;
    const int pix0 = blockIdx.x * 128;
    const int ch0 = blockIdx.y * 64;
    const float* src = (blockIdx.z ? s1 : s0) + (size_t)ch0 * HW;
    dhi += (size_t)blockIdx.z * HW * 128;
    dlo += (size_t)blockIdx.z * HW * 128;
    for (int c = 0; c < 64; c++) s[c * 130 + t] = src[(size_t)c * HW + pix0 + t];
    __syncthreads();
    for (int i = 0; i < 64; i++) {
        int L = t + i * 128;
        int pix = L >> 6, c = L & 63;
        float v = s[c * 130 + pix];
        __half h = __float2half_rn(v);
        size_t di = (size_t)(pix0 + pix) * 128 + ch0 + c;
        dhi[di] = h;
        dlo[di] = __float2half_rn(v - __half2float(h));
    }
}

__device__ __forceinline__ void mma16816(float* d, const u32* a, u32 b0, u32 b1) {
    asm volatile(
        "mma.sync.aligned.m16n8k16.row.col.f32.f16.f16.f32 "
        "{%0,%1,%2,%3}, {%4,%5,%6,%7}, {%8,%9}, {%0,%1,%2,%3};"
        : "+f"(d[0]), "+f"(d[1]), "+f"(d[2]), "+f"(d[3])
        : "r"(a[0]), "r"(a[1]), "r"(a[2]), "r"(a[3]), "r"(b0), "r"(b1));
}
__device__ __forceinline__ void ldsm4(u32* r, u32 addr) {
    asm volatile("ldmatrix.sync.aligned.m8n8.x4.shared.b16 {%0,%1,%2,%3}, [%4];"
                 : "=r"(r[0]), "=r"(r[1]), "=r"(r[2]), "=r"(r[3]) : "r"(addr));
}
__device__ __forceinline__ u32 smem_u32(const void* p) {
    return (u32)__cvta_generic_to_shared(p);
}
__device__ __forceinline__ void cp_async16(void* dst, const void* src, int sb) {
    asm volatile("cp.async.cg.shared.global [%0], [%1], 16, %2;\n"
                 :: "r"(smem_u32(dst)), "l"(src), "r"(sb) : "memory");
}
__device__ __forceinline__ void cp_commit() {
    asm volatile("cp.async.commit_group;\n" ::: "memory");
}
template<int N>
__device__ __forceinline__ void cp_wait() {
    asm volatile("cp.async.wait_group %0;\n" :: "n"(N) : "memory");
}

// per-branch pointer bundle
struct BP {
    const __half* inhi; const __half* inlo;
    const float* bias;
    float* outf; float* outf2;
    const float* flow;
    __half* outhi; __half* outlo;
};

// ---------------- HMMA implicit-GEMM 3x3 conv (all-NHWC cp.async staging) ----------------
// MODE: 0 = lrelu -> hi/lo NHWC(64); 1 = plain -> fp32 NCHW (2-term split); 2 = offxform.
#define GSM 75264
template<int NCB, int MODE>
__global__ __launch_bounds__(256)
void gconv_kernel(BP b0, BP b1, const __half* __restrict__ whi_,
                  const __half* __restrict__ wlo_, int wdelta,
                  int oc_total, int OCpad, int cstr)
{
    extern __shared__ char smem_[];
    __half* sAhi = (__half*)smem_;
    __half* sAlo = (__half*)(smem_ + 27200);
    __half* sWb  = (__half*)(smem_ + 54400);
    float* sbias = (float*)(smem_ + 74880);

    const int br = blockIdx.z;
    const BP b = br ? b1 : b0;
    const __half* whi = whi_ + br * wdelta;
    const __half* wlo = wlo_ + br * wdelta;

    const int tid = threadIdx.x;
    const int wid = tid >> 5, lane = tid & 31;
    const int h0 = (blockIdx.x >> 3) * 8;
    const int w00 = (blockIdx.x & 7) * 32;
    const int ocb = blockIdx.y * 64;
    const int CIN = NCB * 64;
    int nfb = (oc_total - ocb + 7) >> 3; if (nfb > 8) nfb = 8;

    const u32 sAhi_a = smem_u32(sAhi), sAlo_a = smem_u32(sAlo);
    const u32 sW_a   = smem_u32(sWb);

    if (tid < 64) sbias[tid] = (ocb + tid < oc_total) ? b.bias[ocb + tid] : 0.f;

    const int wo = tid >> 2, wq = (tid & 3) * 8;

    float acc0[8][4], acc1[8][4];
#pragma unroll
    for (int i = 0; i < 8; i++)
#pragma unroll
        for (int j = 0; j < 4; j++) { acc0[i][j] = 0.f; acc1[i][j] = 0.f; }

    const int a_dp = (lane & 7) + ((lane >> 3) & 1) * 8;
    const int a_dc = (lane >> 4) * 8;
    const int b_dn = (lane & 7) + ((lane >> 4) & 1) * 8;
    const int b_dc = ((lane >> 3) & 1) * 8;

    for (int cb = 0; cb < NCB; cb++)
    for (int hf = 0; hf < 2; hf++) {
        const int c0 = cb * 64 + hf * 32;
        __syncthreads();
        // ---- hi/lo NHWC staging: pure cp.async ----
#pragma unroll
        for (int i = 0; i < 11; i++) {
            int j = tid + i * 256;
            if (j < 2720) {
                int plane = (j >= 1360) ? 1 : 0;
                int jj = j - plane * 1360;
                int p = jj >> 2, q = jj & 3;
                int rr = p / 34, s = p - rr * 34;
                int gh = h0 - 1 + rr, gw = w00 - 1 + s;
                bool v = ((unsigned)gh < Hd) && ((unsigned)gw < Wd);
                const __half* base = plane ? b.inlo : b.inhi;
                const __half* src = v ? (base + (size_t)(gh * Wd + gw) * cstr + c0 + q * 8)
                                      : base;
                __half* dst = (plane ? sAlo : sAhi) + p * 40 + q * 8;
                cp_async16(dst, src, v ? 16 : 0);
            }
        }
        cp_commit();
        cp_wait<0>();
        {
            size_t gi = (size_t)(0 * OCpad + ocb + wo) * CIN + c0 + wq;
            *(uint4*)&sWb[0 * 2560 + wo * 40 + wq] = *(const uint4*)&whi[gi];
            if (MODE != 1)
                *(uint4*)&sWb[5120 + 0 * 2560 + wo * 40 + wq] = *(const uint4*)&wlo[gi];
        }

        for (int tap = 0; tap < 9; tap++) {
            __syncthreads();
            const int buf = tap & 1;
            if (tap < 8) {
                const int nb = (tap + 1) & 1;
                size_t gi = (size_t)((tap + 1) * OCpad + ocb + wo) * CIN + c0 + wq;
                *(uint4*)&sWb[nb * 2560 + wo * 40 + wq] = *(const uint4*)&whi[gi];
                if (MODE != 1)
                    *(uint4*)&sWb[5120 + nb * 2560 + wo * 40 + wq] = *(const uint4*)&wlo[gi];
            }
            const u32 whi_a = sW_a + buf * 5120;
            const u32 wlo_a = whi_a + 10240;
            const int pb0 = (tap / 3 + wid) * 34 + (tap % 3);
#pragma unroll
            for (int ks = 0; ks < 2; ks++) {
                const int kc = ks * 16;
                const int ch = kc + a_dc;
                u32 ah0[4], al0[4], ah1[4], al1[4];
                ldsm4(ah0, sAhi_a + ((pb0 + a_dp) * 40 + ch) * 2);
                ldsm4(al0, sAlo_a + ((pb0 + a_dp) * 40 + ch) * 2);
                ldsm4(ah1, sAhi_a + ((pb0 + 16 + a_dp) * 40 + ch) * 2);
                ldsm4(al1, sAlo_a + ((pb0 + 16 + a_dp) * 40 + ch) * 2);
#pragma unroll
                for (int pr = 0; pr < 4; pr++) {
                    if (pr * 2 < nfb) {
                        const int n = pr * 16 + b_dn;
                        const u32 wo32 = (n * 40 + kc + b_dc) * 2;
                        u32 bh[4], bl[4];
                        ldsm4(bh, whi_a + wo32);
                        if (MODE != 1) ldsm4(bl, wlo_a + wo32);
                        const int nf = pr * 2;
                        mma16816(acc0[nf], ah0, bh[0], bh[1]);
                        mma16816(acc0[nf], al0, bh[0], bh[1]);
                        mma16816(acc1[nf], ah1, bh[0], bh[1]);
                        mma16816(acc1[nf], al1, bh[0], bh[1]);
                        if (MODE != 1) {
                            mma16816(acc0[nf], ah0, bl[0], bl[1]);
                            mma16816(acc1[nf], ah1, bl[0], bl[1]);
                        }
                        if (nf + 1 < nfb) {
                            mma16816(acc0[nf+1], ah0, bh[2], bh[3]);
                            mma16816(acc0[nf+1], al0, bh[2], bh[3]);
                            mma16816(acc1[nf+1], ah1, bh[2], bh[3]);
                            mma16816(acc1[nf+1], al1, bh[2], bh[3]);
                            if (MODE != 1) {
                                mma16816(acc0[nf+1], ah0, bl[2], bl[3]);
                                mma16816(acc1[nf+1], ah1, bl[2], bl[3]);
                            }
                        }
                    }
                }
            }
        }
    }

    const int row = h0 + wid;
    const int pcol = w00 + (lane >> 2);
    const int ocl = (lane & 3) * 2;
#pragma unroll
    for (int nf = 0; nf < 8; nf++) {
        if (nf >= nfb) break;
        const int oc = ocb + nf * 8 + ocl;
        const float bb0 = sbias[nf * 8 + ocl], bb1 = sbias[nf * 8 + ocl + 1];
#pragma unroll
        for (int sl = 0; sl < 2; sl++) {
            const float* a = sl ? acc1[nf] : acc0[nf];
#pragma unroll
            for (int half_ = 0; half_ < 2; half_++) {
                const int px = row * Wd + pcol + sl * 16 + half_ * 8;
                float r0 = a[half_ * 2 + 0] + bb0;
                float r1 = a[half_ * 2 + 1] + bb1;
                if (MODE == 0) {
                    r0 = (r0 >= 0.f) ? r0 : 0.1f * r0;
                    r1 = (r1 >= 0.f) ? r1 : 0.1f * r1;
                    __half h0v = __float2half_rn(r0), h1v = __float2half_rn(r1);
                    __half l0v = __float2half_rn(r0 - __half2float(h0v));
                    __half l1v = __float2half_rn(r1 - __half2float(h1v));
                    *(__half2*)&b.outhi[(size_t)px * 64 + oc] = __halves2half2(h0v, h1v);
                    *(__half2*)&b.outlo[(size_t)px * 64 + oc] = __halves2half2(l0v, l1v);
                } else if (MODE == 1) {
                    b.outf[(size_t)oc * HW + px] = r0;
                    b.outf[(size_t)(oc + 1) * HW + px] = r1;
                } else {
                    float rr[2] = {r0, r1};
#pragma unroll
                    for (int t = 0; t < 2; t++) {
                        const int o2 = oc + t;
                        if (o2 < 144) {
                            b.outf[(size_t)o2 * HW + px] =
                                10.0f * tanhf(rr[t]) + b.flow[((size_t)((o2 & 1) ^ 1)) * HW + px];
                        } else if (o2 < 216) {
                            b.outf2[(size_t)(o2 - 144) * HW + px] = 1.0f / (1.0f + expf(-rr[t]));
                        }
                    }
                }
            }
        }
    }
}

// ---------------- mdcn (branch-merged, 2-term GEMM, hi/lo NHWC out) ----------------
__global__ __launch_bounds__(256)
void mdcn_kernel(const __half* __restrict__ xt, const float* __restrict__ off,
                 const float* __restrict__ mask, const __half* __restrict__ dwhi,
                 const float* __restrict__ bias0, const float* __restrict__ bias1,
                 __half* __restrict__ cathi, __half* __restrict__ catlo)
{
    __shared__ __align__(16) __half sShi[64 * 90], sSlo[64 * 90];
    __shared__ __align__(16) __half sWhi[64 * 88];
    __shared__ float sbias[64];
    const int br = blockIdx.z;
    xt   += (size_t)br * 64 * HW;
    off  += (size_t)br * 144 * HW;
    mask += (size_t)br * 72 * HW;
    dwhi += br * 45056;
    const int occat = br * 64;           // channel offset in 128-wide cat
    const float* bias = br ? bias1 : bias0;

    const int tid = threadIdx.x;
    const int wid = tid >> 5, lane = tid & 31;
    const int h = blockIdx.y;
    const int col0 = blockIdx.x * 64;
    const int px = tid & 63;
    const int part = tid >> 6;
    const int pixg = col0 + px;
    const int hw = h * Wd + pixg;
    const int k_beg = (part == 0) ? 0 : 1 + part * 2;
    const int k_end = (part == 0) ? 3 : 3 + part * 2;

    if (tid < 64) sbias[tid] = bias[tid];
    for (int i = tid; i < 64 * 8; i += 256) {
        int p = i >> 3, j = i & 7;
        sShi[p * 90 + 72 + j] = __ushort_as_half(0);
        sSlo[p * 90 + 72 + j] = __ushort_as_half(0);
    }

    float acc[8][4];
#pragma unroll
    for (int i = 0; i < 8; i++)
#pragma unroll
        for (int j = 0; j < 4; j++) acc[i][j] = 0.f;

    for (int g = 0; g < 8; g++) {
        __syncthreads();
        {
            const u32* gh32 = (const u32*)(dwhi + g * 5632);
            for (int i = tid; i < 2816; i += 256) ((u32*)sWhi)[i] = gh32[i];
        }
        for (int k = k_beg; k < k_end; k++) {
            int gk = g * 9 + k;
            float offy = off[(gk * 2 + 0) * HW + hw];
            float offx = off[(gk * 2 + 1) * HW + hw];
            float m    = mask[gk * HW + hw];
            float py = (float)h    + (float)(k / 3 - 1) + offy;
            float pxf = (float)pixg + (float)(k % 3 - 1) + offx;
            float y0f = floorf(py), x0f = floorf(pxf);
            float ly = py - y0f, lx = pxf - x0f;
            int y0 = (int)y0f, x0i = (int)x0f;
            int y1 = y0 + 1,  x1 = x0i + 1;
            bool vy0 = (unsigned)y0 < Hd, vy1 = (unsigned)y1 < Hd;
            bool vx0 = (unsigned)x0i < Wd, vx1 = (unsigned)x1 < Wd;
            int yc0 = min(max(y0, 0), Hd - 1), yc1 = min(max(y1, 0), Hd - 1);
            int xc0 = min(max(x0i, 0), Wd - 1), xc1 = min(max(x1, 0), Wd - 1);
            float w00 = (vy0 && vx0) ? (1.f - ly) * (1.f - lx) * m : 0.f;
            float w01 = (vy0 && vx1) ? (1.f - ly) * lx * m : 0.f;
            float w10 = (vy1 && vx0) ? ly * (1.f - lx) * m : 0.f;
            float w11 = (vy1 && vx1) ? ly * lx * m : 0.f;
            uint4 r00 = *(const uint4*)(xt + ((size_t)(yc0 * Wd + xc0)) * 64 + g * 8);
            uint4 r01 = *(const uint4*)(xt + ((size_t)(yc0 * Wd + xc1)) * 64 + g * 8);
            uint4 r10 = *(const uint4*)(xt + ((size_t)(yc1 * Wd + xc0)) * 64 + g * 8);
            uint4 r11 = *(const uint4*)(xt + ((size_t)(yc1 * Wd + xc1)) * 64 + g * 8);
            const __half2* hA = (const __half2*)&r00;
            const __half2* hB = (const __half2*)&r01;
            const __half2* hC = (const __half2*)&r10;
            const __half2* hD = (const __half2*)&r11;
#pragma unroll
            for (int cc = 0; cc < 4; cc++) {
                float2 fa = __half22float2(hA[cc]);
                float2 fb = __half22float2(hB[cc]);
                float2 fc = __half22float2(hC[cc]);
                float2 fd = __half22float2(hD[cc]);
                float s0 = w00 * fa.x + w01 * fb.x + w10 * fc.x + w11 * fd.x;
                float s1 = w00 * fa.y + w01 * fb.y + w10 * fc.y + w11 * fd.y;
                __half h0 = __float2half_rn(s0), h1 = __float2half_rn(s1);
                sShi[px * 90 + (cc * 2 + 0) * 9 + k] = h0;
                sShi[px * 90 + (cc * 2 + 1) * 9 + k] = h1;
                sSlo[px * 90 + (cc * 2 + 0) * 9 + k] = __float2half_rn(s0 - __half2float(h0));
                sSlo[px * 90 + (cc * 2 + 1) * 9 + k] = __float2half_rn(s1 - __half2float(h1));
            }
        }
        __syncthreads();
        const int mw = wid & 3;
        const int nhalf = (wid >> 2) * 4;
        const int r = mw * 16 + (lane >> 2);
#pragma unroll
        for (int ks = 0; ks < 5; ks++) {
            const int kc = ks * 16 + (lane & 3) * 2;
            u32 ah[4], al[4];
            ah[0] = *(const u32*)&sShi[r * 90 + kc];
            ah[1] = *(const u32*)&sShi[(r + 8) * 90 + kc];
            ah[2] = *(const u32*)&sShi[r * 90 + kc + 8];
            ah[3] = *(const u32*)&sShi[(r + 8) * 90 + kc + 8];
            al[0] = *(const u32*)&sSlo[r * 90 + kc];
            al[1] = *(const u32*)&sSlo[(r + 8) * 90 + kc];
            al[2] = *(const u32*)&sSlo[r * 90 + kc + 8];
            al[3] = *(const u32*)&sSlo[(r + 8) * 90 + kc + 8];
#pragma unroll
            for (int nf = 0; nf < 4; nf++) {
                const int n = (nhalf + nf) * 8 + (lane >> 2);
                u32 bh0 = *(const u32*)&sWhi[n * 88 + kc];
                u32 bh1 = *(const u32*)&sWhi[n * 88 + kc + 8];
                mma16816(acc[nf], ah, bh0, bh1);
                mma16816(acc[nf], al, bh0, bh1);
            }
        }
    }
    const int mw = wid & 3, nhalf = (wid >> 2) * 4;
    const int p1 = (size_t)0 + col0 + mw * 16 + (lane >> 2);
    const int oc0 = (lane & 3) * 2;
#pragma unroll
    for (int nf = 0; nf < 4; nf++) {
        const int oc = (nhalf + nf) * 8 + oc0;
        const float bb0 = sbias[oc], bb1 = sbias[oc + 1];
#pragma unroll
        for (int e = 0; e < 2; e++) {
            const int px = h * Wd + p1 + e * 8;
            float r0 = acc[nf][e * 2 + 0] + bb0;
            float r1 = acc[nf][e * 2 + 1] + bb1;
            __half h0v = __float2half_rn(r0), h1v = __float2half_rn(r1);
            __half l0v = __float2half_rn(r0 - __half2float(h0v));
            __half l1v = __float2half_rn(r1 - __half2float(h1v));
            *(__half2*)&cathi[(size_t)px * 128 + occat + oc] = __halves2half2(h0v, h1v);
            *(__half2*)&catlo[(size_t)px * 128 + occat + oc] = __halves2half2(l0v, l1v);
        }
    }
}

// ---------------- host orchestration ----------------
extern "C" void kernel_launch(void* const* d_in, const int* in_sizes, int n_in,
                              void* d_out, int out_size)
{
    const float* feat_prev       = (const float*)d_in[0];
    const float* feat_next       = (const float*)d_in[1];
    const float* extra_feat_prev = (const float*)d_in[2];
    const float* extra_feat_next = (const float*)d_in[3];
    const float* flow_prev       = (const float*)d_in[4];
    const float* flow_next       = (const float*)d_in[5];
    const float* o1b[4] = {(const float*)d_in[7],  (const float*)d_in[9],
                           (const float*)d_in[11], (const float*)d_in[13]};
    const float* o2b[4] = {(const float*)d_in[15], (const float*)d_in[17],
                           (const float*)d_in[19], (const float*)d_in[21]};
    const float* dcn1_w = (const float*)d_in[22];
    const float* dcn1_b = (const float*)d_in[23];
    const float* dcn2_w = (const float*)d_in[24];
    const float* dcn2_b = (const float*)d_in[25];
    const float* fus_b  = (const float*)d_in[27];
    float* out = (float*)d_out;

    float *offp, *maskp;
    __half *xt, *whi, *wlo, *dwhi, *dwlo, *ahi, *alo, *efhi, *eflo, *cathi, *catlo;
    cudaGetSymbolAddress((void**)&offp,  g_off);
    cudaGetSymbolAddress((void**)&maskp, g_mask);
    cudaGetSymbolAddress((void**)&xt,    g_xt);
    cudaGetSymbolAddress((void**)&whi, g_whi);
    cudaGetSymbolAddress((void**)&wlo, g_wlo);
    cudaGetSymbolAddress((void**)&dwhi, g_dwhi);
    cudaGetSymbolAddress((void**)&dwlo, g_dwlo);
    cudaGetSymbolAddress((void**)&ahi, g_act_hi);
    cudaGetSymbolAddress((void**)&alo, g_act_lo);
    cudaGetSymbolAddress((void**)&efhi, g_ef_hi);
    cudaGetSymbolAddress((void**)&eflo, g_ef_lo);
    cudaGetSymbolAddress((void**)&cathi, g_cat_hi);
    cudaGetSymbolAddress((void**)&catlo, g_cat_lo);

    cudaFuncSetAttribute(gconv_kernel<2,0>, cudaFuncAttributeMaxDynamicSharedMemorySize, GSM);
    cudaFuncSetAttribute(gconv_kernel<1,0>, cudaFuncAttributeMaxDynamicSharedMemorySize, GSM);
    cudaFuncSetAttribute(gconv_kernel<1,2>, cudaFuncAttributeMaxDynamicSharedMemorySize, GSM);
    cudaFuncSetAttribute(gconv_kernel<2,1>, cudaFuncAttributeMaxDynamicSharedMemorySize, GSM);

    WSrc ws;
    ws.p[0] = (const float*)d_in[6];  ws.p[1] = (const float*)d_in[8];
    ws.p[2] = (const float*)d_in[10]; ws.p[3] = (const float*)d_in[12];
    ws.p[4] = (const float*)d_in[14]; ws.p[5] = (const float*)d_in[16];
    ws.p[6] = (const float*)d_in[18]; ws.p[7] = (const float*)d_in[20];
    ws.p[8] = (const float*)d_in[26];
    wprep_all<<<(663552 + 255) / 256, 256>>>(ws, whi, wlo);
    dcnprep_all<<<dim3(176, 2), 256>>>(dcn1_w, dcn2_w, dwhi, dwlo);
    tohwc_kernel<<<dim3(512, 2), 128>>>(feat_prev, feat_next, xt);
    efprep_kernel<<<dim3(512, 2, 2), 128>>>(extra_feat_prev, extra_feat_next, efhi, eflo);

    const size_t S = (size_t)HW * 64;
    const size_t EF = (size_t)HW * 128;
    auto mkBP = [&](const __half* ihi, const __half* ilo, const float* bias,
                    float* outf, float* outf2, const float* flow,
                    __half* ohi, __half* olo) {
        BP b; b.inhi = ihi; b.inlo = ilo; b.bias = bias;
        b.outf = outf; b.outf2 = outf2; b.flow = flow; b.outhi = ohi; b.outlo = olo;
        return b;
    };
    __half *hi00 = ahi + 0 * S, *lo00 = alo + 0 * S;
    __half *hi01 = ahi + 1 * S, *lo01 = alo + 1 * S;
    __half *hi10 = ahi + 2 * S, *lo10 = alo + 2 * S;
    __half *hi11 = ahi + 3 * S, *lo11 = alo + 3 * S;

    dim3 g2(256, 1, 2), g42(256, 4, 2), mg2(4, 256, 2), gf(256, 1, 1);

    // L1: ef (stride 128) -> pp0
    gconv_kernel<2,0><<<g2, 256, GSM>>>(
        mkBP(efhi, eflo, o1b[0], nullptr, nullptr, nullptr, hi00, lo00),
        mkBP(efhi + EF, eflo + EF, o2b[0], nullptr, nullptr, nullptr, hi01, lo01),
        whi, wlo, 294912, 64, 64, 128);
    // L2: pp0 -> pp1
    gconv_kernel<1,0><<<g2, 256, GSM>>>(
        mkBP(hi00, lo00, o1b[1], nullptr, nullptr, nullptr, hi10, lo10),
        mkBP(hi01, lo01, o2b[1], nullptr, nullptr, nullptr, hi11, lo11),
        whi + 73728, wlo + 73728, 294912, 64, 64, 64);
    // L3: pp1 -> pp0
    gconv_kernel<1,0><<<g2, 256, GSM>>>(
        mkBP(hi10, lo10, o1b[2], nullptr, nullptr, nullptr, hi00, lo00),
        mkBP(hi11, lo11, o2b[2], nullptr, nullptr, nullptr, hi01, lo01),
        whi + 110592, wlo + 110592, 294912, 64, 64, 64);
    // L4: pp0 -> off/mask
    gconv_kernel<1,2><<<g42, 256, GSM>>>(
        mkBP(hi00, lo00, o1b[3], offp, maskp, flow_prev, nullptr, nullptr),
        mkBP(hi01, lo01, o2b[3], offp + (size_t)144 * HW, maskp + (size_t)72 * HW,
             flow_next, nullptr, nullptr),
        whi + 147456, wlo + 147456, 294912, 216, 256, 64);
    // mdcn both branches -> cat hi/lo NHWC(128)
    mdcn_kernel<<<mg2, 256>>>(xt, offp, maskp, dwhi, dcn1_b, dcn2_b, cathi, catlo);
    // fusion: cat (stride 128) -> out fp32 NCHW, 2-term split
    gconv_kernel<2,1><<<gf, 256, GSM>>>(
        mkBP(cathi, catlo, fus_b, out, nullptr, nullptr, nullptr, nullptr),
        mkBP(cathi, catlo, fus_b, out, nullptr, nullptr, nullptr, nullptr),
        whi + 589824, wlo + 589824, 0, 64, 64, 128);
}

// round 17
// speedup vs baseline: 1.1074x; 1.1074x over previous
#include <cuda_runtime.h>
#include <cuda_fp16.h>
#include <math.h>

#define Wd 256
#define Hd 256
#define HW 65536
typedef unsigned int u32;

// ---------------- scratch (no allocation allowed) ----------------
__device__ float g_off [2 * 144 * HW];
__device__ float g_mask[2 * 72 * HW];
__device__ float g_cat [128 * HW];
__device__ __align__(16) __half g_xt[2 * 64 * HW];           // NHWC feat per branch
__device__ __align__(16) __half g_act_hi[4 * HW * 64];       // [pp*2+branch]
__device__ __align__(16) __half g_act_lo[4 * HW * 64];
__device__ __align__(16) __half g_whi[663552];
__device__ __align__(16) __half g_wlo[663552];
__device__ __align__(16) __half g_dwhi[2 * 45056];

// ---------------- merged conv-weight pre-convert ----------------
struct WSrc { const float* p[9]; };
__global__ void wprep_all(WSrc ws, __half* __restrict__ dhi, __half* __restrict__ dlo)
{
    const int off[9]  = {0,73728,110592,147456,294912,368640,405504,442368,589824};
    const int CINs[9] = {128,64,64,64,128,64,64,64,128};
    const int OCs[9]  = {64,64,64,216,64,64,64,216,64};
    const int OCp[9]  = {64,64,64,256,64,64,64,256,64};
    int idx = blockIdx.x * 256 + threadIdx.x;
    if (idx >= 663552) return;
    int seg = 0;
#pragma unroll
    for (int s = 1; s < 9; s++) if (idx >= off[s]) seg = s;
    int r = idx - off[seg];
    int per_t = OCp[seg] * CINs[seg];
    int t = r / per_t; r -= t * per_t;
    int o = r / CINs[seg], c = r - o * CINs[seg];
    float w = (o < OCs[seg]) ? ws.p[seg][(o * CINs[seg] + c) * 9 + t] : 0.f;
    __half h = __float2half_rn(w);
    dhi[idx] = h;
    dlo[idx] = __float2half_rn(w - __half2float(h));
}

// ---------------- dcn weight pre-convert (hi only, 2-term GEMM) ----------------
__global__ void dcnprep_all(const float* __restrict__ s1, const float* __restrict__ s2,
                            __half* __restrict__ dhi)
{
    int idx = blockIdx.x * 256 + threadIdx.x;
    if (idx >= 45056) return;
    const float* src = blockIdx.y ? s2 : s1;
    int base = blockIdx.y * 45056;
    int g = idx / 5632, r = idx - g * 5632, o = r / 88, ck = r - o * 88;
    float w = 0.f;
    if (ck < 72) { int c = ck / 9, k = ck - c * 9; w = src[((size_t)o * 64 + g * 8 + c) * 9 + k]; }
    dhi[base + idx] = __float2half_rn(w);
}

// ---------------- NCHW fp32 -> NHWC fp16 (both feats) ----------------
__global__ __launch_bounds__(128)
void tohwc_kernel(const float* __restrict__ s0, const float* __restrict__ s1,
                  __half* __restrict__ dst)
{
    __shared__ float s[64 * 130];
    const int t = threadIdx.x;
    const int pix0 = blockIdx.x * 128;
    const float* src = blockIdx.y ? s1 : s0;
    dst += (size_t)blockIdx.y * 64 * HW;
    for (int c = 0; c < 64; c++) s[c * 130 + t] = src[(size_t)c * HW + pix0 + t];
    __syncthreads();
    for (int i = 0; i < 64; i++) {
        int L = t + i * 128;
        dst[(size_t)pix0 * 64 + L] = __float2half_rn(s[(L & 63) * 130 + (L >> 6)]);
    }
}

__device__ __forceinline__ void mma16816(float* d, const u32* a, u32 b0, u32 b1) {
    asm volatile(
        "mma.sync.aligned.m16n8k16.row.col.f32.f16.f16.f32 "
        "{%0,%1,%2,%3}, {%4,%5,%6,%7}, {%8,%9}, {%0,%1,%2,%3};"
        : "+f"(d[0]), "+f"(d[1]), "+f"(d[2]), "+f"(d[3])
        : "r"(a[0]), "r"(a[1]), "r"(a[2]), "r"(a[3]), "r"(b0), "r"(b1));
}
__device__ __forceinline__ void ldsm4(u32* r, u32 addr) {
    asm volatile("ldmatrix.sync.aligned.m8n8.x4.shared.b16 {%0,%1,%2,%3}, [%4];"
                 : "=r"(r[0]), "=r"(r[1]), "=r"(r[2]), "=r"(r[3]) : "r"(addr));
}
__device__ __forceinline__ u32 smem_u32(const void* p) {
    return (u32)__cvta_generic_to_shared(p);
}
__device__ __forceinline__ void cp_async16(void* dst, const void* src, int sb) {
    asm volatile("cp.async.cg.shared.global [%0], [%1], 16, %2;\n"
                 :: "r"(smem_u32(dst)), "l"(src), "r"(sb) : "memory");
}
__device__ __forceinline__ void cp_commit() {
    asm volatile("cp.async.commit_group;\n" ::: "memory");
}
template<int N>
__device__ __forceinline__ void cp_wait() {
    asm volatile("cp.async.wait_group %0;\n" :: "n"(N) : "memory");
}

// per-branch pointer bundle
struct BP {
    const float* in;
    const __half* inhi; const __half* inlo;
    const float* bias;
    float* outf; float* outf2;
    const float* flow;
    __half* outhi; __half* outlo;
};

// ---------------- HMMA implicit-GEMM 3x3 conv (branch-merged) ----------------
// MODE: 0 lrelu->hi/lo NHWC; 1 plain->fp32 NCHW (2-term); 2 offxform (3-term).
#define GSM 75264
template<int NCB, int MODE, int INFMT>
__global__ __launch_bounds__(256)
void gconv_kernel(BP b0, BP b1, const __half* __restrict__ whi_,
                  const __half* __restrict__ wlo_, int wdelta,
                  int oc_total, int OCpad)
{
    extern __shared__ char smem_[];
    __half* sAhi = (__half*)smem_;
    __half* sAlo = (__half*)(smem_ + 27200);
    __half* sWb  = (__half*)(smem_ + 54400);
    float* sbias = (float*)(smem_ + 74880);

    const int br = blockIdx.z;
    const BP b = br ? b1 : b0;
    const __half* whi = whi_ + br * wdelta;
    const __half* wlo = wlo_ + br * wdelta;

    const int tid = threadIdx.x;
    const int wid = tid >> 5, lane = tid & 31;
    const int h0 = (blockIdx.x >> 3) * 8;
    const int w00 = (blockIdx.x & 7) * 32;
    const int ocb = blockIdx.y * 64;
    const int CIN = NCB * 64;
    int nfb = (oc_total - ocb + 7) >> 3; if (nfb > 8) nfb = 8;

    const u32 sAhi_a = smem_u32(sAhi), sAlo_a = smem_u32(sAlo);
    const u32 sW_a   = smem_u32(sWb);

    if (tid < 64) sbias[tid] = (ocb + tid < oc_total) ? b.bias[ocb + tid] : 0.f;

    const int wo = tid >> 2, wq = (tid & 3) * 8;

    float acc0[8][4], acc1[8][4];
#pragma unroll
    for (int i = 0; i < 8; i++)
#pragma unroll
        for (int j = 0; j < 4; j++) { acc0[i][j] = 0.f; acc1[i][j] = 0.f; }

    const int a_dp = (lane & 7) + ((lane >> 3) & 1) * 8;
    const int a_dc = (lane >> 4) * 8;
    const int b_dn = (lane & 7) + ((lane >> 4) & 1) * 8;
    const int b_dc = ((lane >> 3) & 1) * 8;

    for (int cb = 0; cb < NCB; cb++)
    for (int hf = 0; hf < 2; hf++) {
        const int c0 = cb * 64 + hf * 32;
        __syncthreads();
        if (INFMT == 0) {
#pragma unroll
            for (int i = 0; i < 5; i++) {
                int j = tid + i * 256;
                int rr = j >> 7, rem = j & 127;
                int cp = rem >> 3, q = rem & 7;
                int gh = h0 - 1 + rr;
                int c = cp * 2;
                float4 va = make_float4(0.f, 0.f, 0.f, 0.f), vb = va;
                if ((unsigned)gh < Hd) {
                    const float* p = b.in + (size_t)(c0 + c) * HW + gh * Wd + (w00 + q * 4);
                    va = *(const float4*)p;
                    vb = *(const float4*)(p + HW);
                }
                float av[4] = {va.x, va.y, va.z, va.w};
                float bv[4] = {vb.x, vb.y, vb.z, vb.w};
                int ptb = rr * 34 + 1 + q * 4;
#pragma unroll
                for (int k = 0; k < 4; k++) {
                    __half ha = __float2half_rn(av[k]), hb = __float2half_rn(bv[k]);
                    __half la = __float2half_rn(av[k] - __half2float(ha));
                    __half lb = __float2half_rn(bv[k] - __half2float(hb));
                    *(__half2*)&sAhi[(ptb + k) * 40 + c] = __halves2half2(ha, hb);
                    *(__half2*)&sAlo[(ptb + k) * 40 + c] = __halves2half2(la, lb);
                }
            }
#pragma unroll
            for (int i = 0; i < 2; i++) {
                int j = tid + i * 256;
                if (j < 320) {
                    int rr = j >> 5, rem = j & 31;
                    int cp = rem >> 1, e = rem & 1;
                    int s = e ? 33 : 0;
                    int gh = h0 - 1 + rr, gw = w00 - 1 + s;
                    int c = cp * 2;
                    float v0 = 0.f, v1 = 0.f;
                    if ((unsigned)gh < Hd && (unsigned)gw < Wd) {
                        const float* p = b.in + (size_t)(c0 + c) * HW + gh * Wd + gw;
                        v0 = p[0]; v1 = p[HW];
                    }
                    __half h0v = __float2half_rn(v0), h1v = __float2half_rn(v1);
                    __half l0v = __float2half_rn(v0 - __half2float(h0v));
                    __half l1v = __float2half_rn(v1 - __half2float(h1v));
                    int pt = rr * 34 + s;
                    *(__half2*)&sAhi[pt * 40 + c] = __halves2half2(h0v, h1v);
                    *(__half2*)&sAlo[pt * 40 + c] = __halves2half2(l0v, l1v);
                }
            }
        } else {
#pragma unroll
            for (int i = 0; i < 11; i++) {
                int j = tid + i * 256;
                if (j < 2720) {
                    int plane = (j >= 1360) ? 1 : 0;
                    int jj = j - plane * 1360;
                    int p = jj >> 2, q = jj & 3;
                    int rr = p / 34, s = p - rr * 34;
                    int gh = h0 - 1 + rr, gw = w00 - 1 + s;
                    bool v = ((unsigned)gh < Hd) && ((unsigned)gw < Wd);
                    const __half* base = plane ? b.inlo : b.inhi;
                    const __half* src = v ? (base + ((size_t)(gh * Wd + gw)) * 64 + c0 + q * 8)
                                          : base;
                    __half* dst = (plane ? sAlo : sAhi) + p * 40 + q * 8;
                    cp_async16(dst, src, v ? 16 : 0);
                }
            }
            cp_commit();
            cp_wait<0>();
        }
        {
            size_t gi = (size_t)(0 * OCpad + ocb + wo) * CIN + c0 + wq;
            *(uint4*)&sWb[0 * 2560 + wo * 40 + wq] = *(const uint4*)&whi[gi];
            if (MODE != 1)
                *(uint4*)&sWb[5120 + 0 * 2560 + wo * 40 + wq] = *(const uint4*)&wlo[gi];
        }

        for (int tap = 0; tap < 9; tap++) {
            __syncthreads();
            const int buf = tap & 1;
            if (tap < 8) {
                const int nb = (tap + 1) & 1;
                size_t gi = (size_t)((tap + 1) * OCpad + ocb + wo) * CIN + c0 + wq;
                *(uint4*)&sWb[nb * 2560 + wo * 40 + wq] = *(const uint4*)&whi[gi];
                if (MODE != 1)
                    *(uint4*)&sWb[5120 + nb * 2560 + wo * 40 + wq] = *(const uint4*)&wlo[gi];
            }
            const u32 whi_a = sW_a + buf * 5120;
            const u32 wlo_a = whi_a + 10240;
            const int pb0 = (tap / 3 + wid) * 34 + (tap % 3);
#pragma unroll
            for (int ks = 0; ks < 2; ks++) {
                const int kc = ks * 16;
                const int ch = kc + a_dc;
                u32 ah0[4], al0[4], ah1[4], al1[4];
                ldsm4(ah0, sAhi_a + ((pb0 + a_dp) * 40 + ch) * 2);
                ldsm4(al0, sAlo_a + ((pb0 + a_dp) * 40 + ch) * 2);
                ldsm4(ah1, sAhi_a + ((pb0 + 16 + a_dp) * 40 + ch) * 2);
                ldsm4(al1, sAlo_a + ((pb0 + 16 + a_dp) * 40 + ch) * 2);
#pragma unroll
                for (int pr = 0; pr < 4; pr++) {
                    if (pr * 2 < nfb) {
                        const int n = pr * 16 + b_dn;
                        const u32 wo32 = (n * 40 + kc + b_dc) * 2;
                        u32 bh[4], bl[4];
                        ldsm4(bh, whi_a + wo32);
                        if (MODE != 1) ldsm4(bl, wlo_a + wo32);
                        const int nf = pr * 2;
                        mma16816(acc0[nf], ah0, bh[0], bh[1]);
                        mma16816(acc0[nf], al0, bh[0], bh[1]);
                        mma16816(acc1[nf], ah1, bh[0], bh[1]);
                        mma16816(acc1[nf], al1, bh[0], bh[1]);
                        if (MODE != 1) {
                            mma16816(acc0[nf], ah0, bl[0], bl[1]);
                            mma16816(acc1[nf], ah1, bl[0], bl[1]);
                        }
                        if (nf + 1 < nfb) {
                            mma16816(acc0[nf+1], ah0, bh[2], bh[3]);
                            mma16816(acc0[nf+1], al0, bh[2], bh[3]);
                            mma16816(acc1[nf+1], ah1, bh[2], bh[3]);
                            mma16816(acc1[nf+1], al1, bh[2], bh[3]);
                            if (MODE != 1) {
                                mma16816(acc0[nf+1], ah0, bl[2], bl[3]);
                                mma16816(acc1[nf+1], ah1, bl[2], bl[3]);
                            }
                        }
                    }
                }
            }
        }
    }

    const int row = h0 + wid;
    const int pcol = w00 + (lane >> 2);
    const int ocl = (lane & 3) * 2;
#pragma unroll
    for (int nf = 0; nf < 8; nf++) {
        if (nf >= nfb) break;
        const int oc = ocb + nf * 8 + ocl;
        const float bb0 = sbias[nf * 8 + ocl], bb1 = sbias[nf * 8 + ocl + 1];
#pragma unroll
        for (int sl = 0; sl < 2; sl++) {
            const float* a = sl ? acc1[nf] : acc0[nf];
#pragma unroll
            for (int half_ = 0; half_ < 2; half_++) {
                const int px = row * Wd + pcol + sl * 16 + half_ * 8;
                float r0 = a[half_ * 2 + 0] + bb0;
                float r1 = a[half_ * 2 + 1] + bb1;
                if (MODE == 0) {
                    r0 = (r0 >= 0.f) ? r0 : 0.1f * r0;
                    r1 = (r1 >= 0.f) ? r1 : 0.1f * r1;
                    __half h0v = __float2half_rn(r0), h1v = __float2half_rn(r1);
                    __half l0v = __float2half_rn(r0 - __half2float(h0v));
                    __half l1v = __float2half_rn(r1 - __half2float(h1v));
                    *(__half2*)&b.outhi[(size_t)px * 64 + oc] = __halves2half2(h0v, h1v);
                    *(__half2*)&b.outlo[(size_t)px * 64 + oc] = __halves2half2(l0v, l1v);
                } else if (MODE == 1) {
                    b.outf[(size_t)oc * HW + px] = r0;
                    b.outf[(size_t)(oc + 1) * HW + px] = r1;
                } else {
                    float rr[2] = {r0, r1};
#pragma unroll
                    for (int t = 0; t < 2; t++) {
                        const int o2 = oc + t;
                        if (o2 < 144) {
                            b.outf[(size_t)o2 * HW + px] =
                                10.0f * tanhf(rr[t]) + b.flow[((size_t)((o2 & 1) ^ 1)) * HW + px];
                        } else if (o2 < 216) {
                            b.outf2[(size_t)(o2 - 144) * HW + px] = 1.0f / (1.0f + expf(-rr[t]));
                        }
                    }
                }
            }
        }
    }
}

// ---------------- mdcn (branch-merged, 2-term GEMM, fp32 NCHW out) ----------------
__global__ __launch_bounds__(256)
void mdcn_kernel(const __half* __restrict__ xt, const float* __restrict__ off,
                 const float* __restrict__ mask, const __half* __restrict__ dwhi,
                 const float* __restrict__ bias0, const float* __restrict__ bias1,
                 float* __restrict__ out)
{
    __shared__ __align__(16) __half sShi[64 * 90], sSlo[64 * 90];
    __shared__ __align__(16) __half sWhi[64 * 88];
    __shared__ float sbias[64];
    const int br = blockIdx.z;
    xt   += (size_t)br * 64 * HW;
    off  += (size_t)br * 144 * HW;
    mask += (size_t)br * 72 * HW;
    dwhi += br * 45056;
    out  += (size_t)br * 64 * HW;
    const float* bias = br ? bias1 : bias0;

    const int tid = threadIdx.x;
    const int wid = tid >> 5, lane = tid & 31;
    const int h = blockIdx.y;
    const int col0 = blockIdx.x * 64;
    const int px = tid & 63;
    const int part = tid >> 6;
    const int pixg = col0 + px;
    const int hw = h * Wd + pixg;
    const int k_beg = (part == 0) ? 0 : 1 + part * 2;
    const int k_end = (part == 0) ? 3 : 3 + part * 2;

    if (tid < 64) sbias[tid] = bias[tid];
    for (int i = tid; i < 64 * 8; i += 256) {
        int p = i >> 3, j = i & 7;
        sShi[p * 90 + 72 + j] = __ushort_as_half(0);
        sSlo[p * 90 + 72 + j] = __ushort_as_half(0);
    }

    float acc[8][4];
#pragma unroll
    for (int i = 0; i < 8; i++)
#pragma unroll
        for (int j = 0; j < 4; j++) acc[i][j] = 0.f;

    for (int g = 0; g < 8; g++) {
        __syncthreads();
        {
            const u32* gh32 = (const u32*)(dwhi + g * 5632);
            for (int i = tid; i < 2816; i += 256) ((u32*)sWhi)[i] = gh32[i];
        }
        for (int k = k_beg; k < k_end; k++) {
            int gk = g * 9 + k;
            float offy = off[(gk * 2 + 0) * HW + hw];
            float offx = off[(gk * 2 + 1) * HW + hw];
            float m    = mask[gk * HW + hw];
            float py = (float)h    + (float)(k / 3 - 1) + offy;
            float pxf = (float)pixg + (float)(k % 3 - 1) + offx;
            float y0f = floorf(py), x0f = floorf(pxf);
            float ly = py - y0f, lx = pxf - x0f;
            int y0 = (int)y0f, x0i = (int)x0f;
            int y1 = y0 + 1,  x1 = x0i + 1;
            bool vy0 = (unsigned)y0 < Hd, vy1 = (unsigned)y1 < Hd;
            bool vx0 = (unsigned)x0i < Wd, vx1 = (unsigned)x1 < Wd;
            int yc0 = min(max(y0, 0), Hd - 1), yc1 = min(max(y1, 0), Hd - 1);
            int xc0 = min(max(x0i, 0), Wd - 1), xc1 = min(max(x1, 0), Wd - 1);
            float w00 = (vy0 && vx0) ? (1.f - ly) * (1.f - lx) * m : 0.f;
            float w01 = (vy0 && vx1) ? (1.f - ly) * lx * m : 0.f;
            float w10 = (vy1 && vx0) ? ly * (1.f - lx) * m : 0.f;
            float w11 = (vy1 && vx1) ? ly * lx * m : 0.f;
            uint4 r00 = *(const uint4*)(xt + ((size_t)(yc0 * Wd + xc0)) * 64 + g * 8);
            uint4 r01 = *(const uint4*)(xt + ((size_t)(yc0 * Wd + xc1)) * 64 + g * 8);
            uint4 r10 = *(const uint4*)(xt + ((size_t)(yc1 * Wd + xc0)) * 64 + g * 8);
            uint4 r11 = *(const uint4*)(xt + ((size_t)(yc1 * Wd + xc1)) * 64 + g * 8);
            const __half2* hA = (const __half2*)&r00;
            const __half2* hB = (const __half2*)&r01;
            const __half2* hC = (const __half2*)&r10;
            const __half2* hD = (const __half2*)&r11;
#pragma unroll
            for (int cc = 0; cc < 4; cc++) {
                float2 fa = __half22float2(hA[cc]);
                float2 fb = __half22float2(hB[cc]);
                float2 fc = __half22float2(hC[cc]);
                float2 fd = __half22float2(hD[cc]);
                float s0 = w00 * fa.x + w01 * fb.x + w10 * fc.x + w11 * fd.x;
                float s1 = w00 * fa.y + w01 * fb.y + w10 * fc.y + w11 * fd.y;
                __half h0 = __float2half_rn(s0), h1 = __float2half_rn(s1);
                sShi[px * 90 + (cc * 2 + 0) * 9 + k] = h0;
                sShi[px * 90 + (cc * 2 + 1) * 9 + k] = h1;
                sSlo[px * 90 + (cc * 2 + 0) * 9 + k] = __float2half_rn(s0 - __half2float(h0));
                sSlo[px * 90 + (cc * 2 + 1) * 9 + k] = __float2half_rn(s1 - __half2float(h1));
            }
        }
        __syncthreads();
        const int mw = wid & 3;
        const int nhalf = (wid >> 2) * 4;
        const int r = mw * 16 + (lane >> 2);
#pragma unroll
        for (int ks = 0; ks < 5; ks++) {
            const int kc = ks * 16 + (lane & 3) * 2;
            u32 ah[4], al[4];
            ah[0] = *(const u32*)&sShi[r * 90 + kc];
            ah[1] = *(const u32*)&sShi[(r + 8) * 90 + kc];
            ah[2] = *(const u32*)&sShi[r * 90 + kc + 8];
            ah[3] = *(const u32*)&sShi[(r + 8) * 90 + kc + 8];
            al[0] = *(const u32*)&sSlo[r * 90 + kc];
            al[1] = *(const u32*)&sSlo[(r + 8) * 90 + kc];
            al[2] = *(const u32*)&sSlo[r * 90 + kc + 8];
            al[3] = *(const u32*)&sSlo[(r + 8) * 90 + kc + 8];
#pragma unroll
            for (int nf = 0; nf < 4; nf++) {
                const int n = (nhalf + nf) * 8 + (lane >> 2);
                u32 bh0 = *(const u32*)&sWhi[n * 88 + kc];
                u32 bh1 = *(const u32*)&sWhi[n * 88 + kc + 8];
                mma16816(acc[nf], ah, bh0, bh1);
                mma16816(acc[nf], al, bh0, bh1);
            }
        }
    }
    const int mw = wid & 3, nhalf = (wid >> 2) * 4;
    const int p1 = col0 + mw * 16 + (lane >> 2);
    const int p2 = p1 + 8;
    const int oc0 = (lane & 3) * 2;
#pragma unroll
    for (int nf = 0; nf < 4; nf++) {
        const int oc = (nhalf + nf) * 8 + oc0;
        out[(size_t)oc * HW + h * Wd + p1]       = acc[nf][0] + sbias[oc];
        out[(size_t)(oc + 1) * HW + h * Wd + p1] = acc[nf][1] + sbias[oc + 1];
        out[(size_t)oc * HW + h * Wd + p2]       = acc[nf][2] + sbias[oc];
        out[(size_t)(oc + 1) * HW + h * Wd + p2] = acc[nf][3] + sbias[oc + 1];
    }
}

// ---------------- host orchestration ----------------
extern "C" void kernel_launch(void* const* d_in, const int* in_sizes, int n_in,
                              void* d_out, int out_size)
{
    const float* feat_prev       = (const float*)d_in[0];
    const float* feat_next       = (const float*)d_in[1];
    const float* extra_feat_prev = (const float*)d_in[2];
    const float* extra_feat_next = (const float*)d_in[3];
    const float* flow_prev       = (const float*)d_in[4];
    const float* flow_next       = (const float*)d_in[5];
    const float* o1b[4] = {(const float*)d_in[7],  (const float*)d_in[9],
                           (const float*)d_in[11], (const float*)d_in[13]};
    const float* o2b[4] = {(const float*)d_in[15], (const float*)d_in[17],
                           (const float*)d_in[19], (const float*)d_in[21]};
    const float* dcn1_w = (const float*)d_in[22];
    const float* dcn1_b = (const float*)d_in[23];
    const float* dcn2_w = (const float*)d_in[24];
    const float* dcn2_b = (const float*)d_in[25];
    const float* fus_b  = (const float*)d_in[27];
    float* out = (float*)d_out;

    float *offp, *maskp, *catp;
    __half *xt, *whi, *wlo, *dwhi, *ahi, *alo;
    cudaGetSymbolAddress((void**)&offp,  g_off);
    cudaGetSymbolAddress((void**)&maskp, g_mask);
    cudaGetSymbolAddress((void**)&catp,  g_cat);
    cudaGetSymbolAddress((void**)&xt,    g_xt);
    cudaGetSymbolAddress((void**)&whi, g_whi);
    cudaGetSymbolAddress((void**)&wlo, g_wlo);
    cudaGetSymbolAddress((void**)&dwhi, g_dwhi);
    cudaGetSymbolAddress((void**)&ahi, g_act_hi);
    cudaGetSymbolAddress((void**)&alo, g_act_lo);

    cudaFuncSetAttribute(gconv_kernel<2,0,0>, cudaFuncAttributeMaxDynamicSharedMemorySize, GSM);
    cudaFuncSetAttribute(gconv_kernel<1,0,1>, cudaFuncAttributeMaxDynamicSharedMemorySize, GSM);
    cudaFuncSetAttribute(gconv_kernel<1,2,1>, cudaFuncAttributeMaxDynamicSharedMemorySize, GSM);
    cudaFuncSetAttribute(gconv_kernel<2,1,0>, cudaFuncAttributeMaxDynamicSharedMemorySize, GSM);

    WSrc ws;
    ws.p[0] = (const float*)d_in[6];  ws.p[1] = (const float*)d_in[8];
    ws.p[2] = (const float*)d_in[10]; ws.p[3] = (const float*)d_in[12];
    ws.p[4] = (const float*)d_in[14]; ws.p[5] = (const float*)d_in[16];
    ws.p[6] = (const float*)d_in[18]; ws.p[7] = (const float*)d_in[20];
    ws.p[8] = (const float*)d_in[26];
    wprep_all<<<(663552 + 255) / 256, 256>>>(ws, whi, wlo);
    dcnprep_all<<<dim3(176, 2), 256>>>(dcn1_w, dcn2_w, dwhi);
    tohwc_kernel<<<dim3(512, 2), 128>>>(feat_prev, feat_next, xt);

    const size_t S = (size_t)HW * 64;
    auto mkBP = [&](const float* in, const __half* ihi, const __half* ilo,
                    const float* bias, float* outf, float* outf2, const float* flow,
                    __half* ohi, __half* olo) {
        BP b; b.in = in; b.inhi = ihi; b.inlo = ilo; b.bias = bias;
        b.outf = outf; b.outf2 = outf2; b.flow = flow; b.outhi = ohi; b.outlo = olo;
        return b;
    };
    __half *hi00 = ahi + 0 * S, *lo00 = alo + 0 * S;
    __half *hi01 = ahi + 1 * S, *lo01 = alo + 1 * S;
    __half *hi10 = ahi + 2 * S, *lo10 = alo + 2 * S;
    __half *hi11 = ahi + 3 * S, *lo11 = alo + 3 * S;

    dim3 g2(256, 1, 2), g42(256, 4, 2), mg2(4, 256, 2), gf(256, 1, 1);

    // L1: extra -> pp0
    gconv_kernel<2,0,0><<<g2, 256, GSM>>>(
        mkBP(extra_feat_prev, nullptr, nullptr, o1b[0], nullptr, nullptr, nullptr, hi00, lo00),
        mkBP(extra_feat_next, nullptr, nullptr, o2b[0], nullptr, nullptr, nullptr, hi01, lo01),
        whi, wlo, 294912, 64, 64);
    // L2: pp0 -> pp1
    gconv_kernel<1,0,1><<<g2, 256, GSM>>>(
        mkBP(nullptr, hi00, lo00, o1b[1], nullptr, nullptr, nullptr, hi10, lo10),
        mkBP(nullptr, hi01, lo01, o2b[1], nullptr, nullptr, nullptr, hi11, lo11),
        whi + 73728, wlo + 73728, 294912, 64, 64);
    // L3: pp1 -> pp0
    gconv_kernel<1,0,1><<<g2, 256, GSM>>>(
        mkBP(nullptr, hi10, lo10, o1b[2], nullptr, nullptr, nullptr, hi00, lo00),
        mkBP(nullptr, hi11, lo11, o2b[2], nullptr, nullptr, nullptr, hi01, lo01),
        whi + 110592, wlo + 110592, 294912, 64, 64);
    // L4: pp0 -> off/mask (per-branch regions)
    gconv_kernel<1,2,1><<<g42, 256, GSM>>>(
        mkBP(nullptr, hi00, lo00, o1b[3], offp, maskp, flow_prev, nullptr, nullptr),
        mkBP(nullptr, hi01, lo01, o2b[3], offp + (size_t)144 * HW, maskp + (size_t)72 * HW,
             flow_next, nullptr, nullptr),
        whi + 147456, wlo + 147456, 294912, 216, 256);
    // mdcn both branches (2-term GEMM)
    mdcn_kernel<<<mg2, 256>>>(xt, offp, maskp, dwhi, dcn1_b, dcn2_b, catp);
    // fusion (2-term split)
    gconv_kernel<2,1,0><<<gf, 256, GSM>>>(
        mkBP(catp, nullptr, nullptr, fus_b, out, nullptr, nullptr, nullptr, nullptr),
        mkBP(catp, nullptr, nullptr, fus_b, out, nullptr, nullptr, nullptr, nullptr),
        whi + 589824, wlo + 589824, 0, 64, 64);
}